// round 4
// baseline (speedup 1.0000x reference)
#include <cuda_runtime.h>

// Problem constants (match reference)
#define N_ATOMS   245760
#define N_PAIRS   16777216
#define N_MOLS    4096
#define KE_CONST  138.96f

// ---------------------------------------------------------------------------
// Kernel 1: initialize output with per_system_energy * KE
// ---------------------------------------------------------------------------
__global__ void init_out_kernel(const float* __restrict__ pse,
                                float* __restrict__ out) {
    int m = blockIdx.x * blockDim.x + threadIdx.x;
    if (m < N_MOLS) out[m] = pse[m] * KE_CONST;
}

// ---------------------------------------------------------------------------
// chi(d) with the phi(2d) attenuation folded in, pre-scaled by KE
// ---------------------------------------------------------------------------
__device__ __forceinline__ float chi_of_d(float d) {
    // phi(u) = 1 - 6u^5 + 15u^4 - 10u^3, u = 2d, zero for u >= 1
    float u  = 2.0f * d;
    float u2 = u * u;
    float u3 = u2 * u;
    float inner = fmaf(-6.0f, u2, fmaf(15.0f, u, -10.0f));
    float phi   = fmaf(u3, inner, 1.0f);
    phi = (u < 1.0f) ? phi : 0.0f;

    float rs = rsqrtf(fmaf(d, d, 1.0f));   // 1/sqrt(d^2+1)
    float rd = __fdividef(1.0f, d);        // 1/d
    return fmaf(phi, rs - rd, rd);         // rd + phi*(rs-rd)
}

// ---------------------------------------------------------------------------
// Kernel 2: main pair loop — gathers on L1, reductions offloaded to L2 (REDG)
// ---------------------------------------------------------------------------
__global__ __launch_bounds__(512, 4)
void coulomb_pairs_kernel(const float* __restrict__ q,
                          const int*   __restrict__ idx_i,
                          const int*   __restrict__ idx_j,
                          const float* __restrict__ d_ij,
                          const int*   __restrict__ seg,
                          float*       __restrict__ out)
{
    const int nquads = N_PAIRS / 4;
    const int stride = gridDim.x * blockDim.x;

    for (int t = blockIdx.x * blockDim.x + threadIdx.x; t < nquads; t += stride) {
        // ---- Streaming loads (evict-first: keep L1 for gathers) ----
        int4   vi = __ldcs(reinterpret_cast<const int4*>(idx_i) + t);
        int4   vj = __ldcs(reinterpret_cast<const int4*>(idx_j) + t);
        float4 vd = __ldcs(reinterpret_cast<const float4*>(d_ij) + t);
        int4   vs = __ldcs(reinterpret_cast<const int4*>(seg)   + t);

        // ---- Batch the 8 random gathers (L1/L2) ----
        float qi0 = __ldg(q + vi.x), qj0 = __ldg(q + vj.x);
        float qi1 = __ldg(q + vi.y), qj1 = __ldg(q + vj.y);
        float qi2 = __ldg(q + vi.z), qj2 = __ldg(q + vj.z);
        float qi3 = __ldg(q + vi.w), qj3 = __ldg(q + vj.w);

        // ---- Compute (KE folded in) ----
        float c0 = qi0 * qj0 * chi_of_d(vd.x) * KE_CONST;
        float c1 = qi1 * qj1 * chi_of_d(vd.y) * KE_CONST;
        float c2 = qi2 * qj2 * chi_of_d(vd.z) * KE_CONST;
        float c3 = qi3 * qj3 * chi_of_d(vd.w) * KE_CONST;

        // ---- Scatter: global RED (LTS-side add, result unused -> REDG) ----
        if (vi.x < vj.x) atomicAdd(out + vs.x, c0);
        if (vi.y < vj.y) atomicAdd(out + vs.y, c1);
        if (vi.z < vj.z) atomicAdd(out + vs.z, c2);
        if (vi.w < vj.w) atomicAdd(out + vs.w, c3);
    }
}

// ---------------------------------------------------------------------------
// Launch
// ---------------------------------------------------------------------------
extern "C" void kernel_launch(void* const* d_in, const int* in_sizes, int n_in,
                              void* d_out, int out_size) {
    const float* q    = (const float*)d_in[0];           // per_atom_charge [N_ATOMS]
    const int*   pidx = (const int*)  d_in[1];           // pair_indices [2, N_PAIRS]
    const float* dij  = (const float*)d_in[2];           // d_ij [N_PAIRS]
    const int*   seg  = (const int*)  d_in[3];           // atomic_subsystem_indices [N_PAIRS]
    const float* pse  = (const float*)d_in[4];           // per_system_energy [N_MOLS]
    float* out = (float*)d_out;

    const int* idx_i = pidx;
    const int* idx_j = pidx + N_PAIRS;

    init_out_kernel<<<(N_MOLS + 255) / 256, 256>>>(pse, out);

    // Proven config: 4 blocks/SM x 148 SMs, 512 threads, 64 warps/SM.
    const int blocks  = 592;
    const int threads = 512;
    coulomb_pairs_kernel<<<blocks, threads>>>(q, idx_i, idx_j, dij, seg, out);
}

// round 5
// speedup vs baseline: 1.4497x; 1.4497x over previous
#include <cuda_runtime.h>
#include <cuda_fp16.h>

// Problem constants (match reference)
#define N_ATOMS   245760
#define N_PAIRS   16777216
#define N_MOLS    4096
#define KE_CONST  138.96f

// fp16 SMEM slice: atoms [0, S_SLICE) are served from shared memory.
// 20224 * 2B = 39.5 KB slice + 16 KB histogram = 55.5 KB dynamic SMEM/block.
// 4 blocks/SM x (56832 + 1024 reserved) = 231424 B <= 233472 B/SM budget.
#define S_SLICE    20224
#define SMEM_BYTES (N_MOLS * sizeof(float) + S_SLICE * sizeof(__half))

// ---------------------------------------------------------------------------
// Kernel 1: initialize output with per_system_energy * KE
// ---------------------------------------------------------------------------
__global__ void init_out_kernel(const float* __restrict__ pse,
                                float* __restrict__ out) {
    int m = blockIdx.x * blockDim.x + threadIdx.x;
    if (m < N_MOLS) out[m] = pse[m] * KE_CONST;
}

// ---------------------------------------------------------------------------
// chi(d) with the phi(2d) attenuation folded in
// ---------------------------------------------------------------------------
__device__ __forceinline__ float chi_of_d(float d) {
    // phi(u) = 1 - 6u^5 + 15u^4 - 10u^3, u = 2d, zero for u >= 1
    float u  = 2.0f * d;
    float u2 = u * u;
    float u3 = u2 * u;
    float inner = fmaf(-6.0f, u2, fmaf(15.0f, u, -10.0f));
    float phi   = fmaf(u3, inner, 1.0f);
    phi = (u < 1.0f) ? phi : 0.0f;

    float rs = rsqrtf(fmaf(d, d, 1.0f));   // 1/sqrt(d^2+1)
    float rd = __fdividef(1.0f, d);        // 1/d
    return fmaf(phi, rs - rd, rd);         // rd + phi*(rs-rd)
}

// Gather: SMEM fp16 slice for low indices (cheap scattered LDS),
// predicated LDG for the rest (wavefronts only for active lanes).
__device__ __forceinline__ float get_q(const float* __restrict__ q,
                                       const __half* __restrict__ qs,
                                       int i) {
    float v;
    if (i < S_SLICE) v = __half2float(qs[i]);
    else             v = __ldg(q + i);
    return v;
}

// ---------------------------------------------------------------------------
// Kernel 2: main pair loop — R1 shell + fp16 slice + branchless atomics
// ---------------------------------------------------------------------------
__global__ __launch_bounds__(512, 4)
void coulomb_pairs_kernel(const float* __restrict__ q,
                          const int*   __restrict__ idx_i,
                          const int*   __restrict__ idx_j,
                          const float* __restrict__ d_ij,
                          const int*   __restrict__ seg,
                          float*       __restrict__ out)
{
    extern __shared__ float smem[];
    float*  acc = smem;                                  // [N_MOLS] 16 KB
    __half* qs  = reinterpret_cast<__half*>(smem + N_MOLS); // [S_SLICE] 39.5 KB

    for (int m = threadIdx.x; m < N_MOLS; m += blockDim.x)
        acc[m] = 0.0f;
    // Stage low 20224 charges into SMEM as fp16 (coalesced reads)
    for (int k = threadIdx.x; k < S_SLICE; k += blockDim.x)
        qs[k] = __float2half(q[k]);
    __syncthreads();

    const int nquads = N_PAIRS / 4;
    const int stride = gridDim.x * blockDim.x;

    for (int t = blockIdx.x * blockDim.x + threadIdx.x; t < nquads; t += stride) {
        // ---- Streaming loads (evict-first: keep L1 for gathers) ----
        int4   vi = __ldcs(reinterpret_cast<const int4*>(idx_i) + t);
        int4   vj = __ldcs(reinterpret_cast<const int4*>(idx_j) + t);
        float4 vd = __ldcs(reinterpret_cast<const float4*>(d_ij) + t);
        int4   vs = __ldcs(reinterpret_cast<const int4*>(seg)   + t);

        // ---- Batch the 8 gathers (SMEM slice or L1/L2) ----
        float qi0 = get_q(q, qs, vi.x), qj0 = get_q(q, qs, vj.x);
        float qi1 = get_q(q, qs, vi.y), qj1 = get_q(q, qs, vj.y);
        float qi2 = get_q(q, qs, vi.z), qj2 = get_q(q, qs, vj.z);
        float qi3 = get_q(q, qs, vi.w), qj3 = get_q(q, qs, vj.w);

        // ---- Compute, fold in unique mask (i<j ~always true; 0.0 add is exact) ----
        float m0 = (vi.x < vj.x) ? 1.0f : 0.0f;
        float m1 = (vi.y < vj.y) ? 1.0f : 0.0f;
        float m2 = (vi.z < vj.z) ? 1.0f : 0.0f;
        float m3 = (vi.w < vj.w) ? 1.0f : 0.0f;

        float c0 = qi0 * qj0 * chi_of_d(vd.x) * m0;
        float c1 = qi1 * qj1 * chi_of_d(vd.y) * m1;
        float c2 = qi2 * qj2 * chi_of_d(vd.z) * m2;
        float c3 = qi3 * qj3 * chi_of_d(vd.w) * m3;

        // ---- Unconditional SMEM scatter (no BSSY/BSYNC) ----
        atomicAdd(&acc[vs.x], c0);
        atomicAdd(&acc[vs.y], c1);
        atomicAdd(&acc[vs.z], c2);
        atomicAdd(&acc[vs.w], c3);
    }

    __syncthreads();

    // Flush block-private histogram (out already holds pse*KE)
    for (int m = threadIdx.x; m < N_MOLS; m += blockDim.x) {
        float v = acc[m];
        if (v != 0.0f)
            atomicAdd(&out[m], v * KE_CONST);
    }
}

// ---------------------------------------------------------------------------
// Launch
// ---------------------------------------------------------------------------
extern "C" void kernel_launch(void* const* d_in, const int* in_sizes, int n_in,
                              void* d_out, int out_size) {
    const float* q    = (const float*)d_in[0];           // per_atom_charge [N_ATOMS]
    const int*   pidx = (const int*)  d_in[1];           // pair_indices [2, N_PAIRS]
    const float* dij  = (const float*)d_in[2];           // d_ij [N_PAIRS]
    const int*   seg  = (const int*)  d_in[3];           // atomic_subsystem_indices [N_PAIRS]
    const float* pse  = (const float*)d_in[4];           // per_system_energy [N_MOLS]
    float* out = (float*)d_out;

    const int* idx_i = pidx;
    const int* idx_j = pidx + N_PAIRS;

    static bool attr_done = false;
    if (!attr_done) {
        cudaFuncSetAttribute(coulomb_pairs_kernel,
                             cudaFuncAttributeMaxDynamicSharedMemorySize,
                             (int)SMEM_BYTES);
        attr_done = true;
    }

    init_out_kernel<<<(N_MOLS + 255) / 256, 256>>>(pse, out);

    // Proven config: 4 blocks/SM x 148 SMs, 512 threads, 64 warps/SM.
    const int blocks  = 592;
    const int threads = 512;
    coulomb_pairs_kernel<<<blocks, threads, SMEM_BYTES>>>(
        q, idx_i, idx_j, dij, seg, out);
}

// round 6
// speedup vs baseline: 3.0019x; 2.0707x over previous
#include <cuda_runtime.h>

// Problem constants (match reference)
#define N_ATOMS   245760
#define N_PAIRS   16777216
#define N_MOLS    4096
#define KE_CONST  138.96f

// ---------------------------------------------------------------------------
// Kernel 1: initialize output with per_system_energy * KE
// ---------------------------------------------------------------------------
__global__ void init_out_kernel(const float* __restrict__ pse,
                                float* __restrict__ out) {
    int m = blockIdx.x * blockDim.x + threadIdx.x;
    if (m < N_MOLS) out[m] = pse[m] * KE_CONST;
}

// ---------------------------------------------------------------------------
// chi(d) with the phi(2d) attenuation folded in
// ---------------------------------------------------------------------------
__device__ __forceinline__ float chi_of_d(float d) {
    // phi(u) = 1 - 6u^5 + 15u^4 - 10u^3, u = 2d, zero for u >= 1
    float u  = 2.0f * d;
    float u2 = u * u;
    float u3 = u2 * u;
    float inner = fmaf(-6.0f, u2, fmaf(15.0f, u, -10.0f));
    float phi   = fmaf(u3, inner, 1.0f);
    phi = (u < 1.0f) ? phi : 0.0f;

    float rs = rsqrtf(fmaf(d, d, 1.0f));   // 1/sqrt(d^2+1)
    float rd = __fdividef(1.0f, d);        // 1/d
    return fmaf(phi, rs - rd, rd);         // rd + phi*(rs-rd)
}

// ---------------------------------------------------------------------------
// Kernel 2: main pair loop — R1 structure, fully branch-free hot loop
// ---------------------------------------------------------------------------
__global__ __launch_bounds__(512, 4)
void coulomb_pairs_kernel(const float* __restrict__ q,
                          const int*   __restrict__ idx_i,
                          const int*   __restrict__ idx_j,
                          const float* __restrict__ d_ij,
                          const int*   __restrict__ seg,
                          float*       __restrict__ out)
{
    __shared__ float acc[N_MOLS];   // 16 KB per-block private histogram

    for (int m = threadIdx.x; m < N_MOLS; m += blockDim.x)
        acc[m] = 0.0f;
    __syncthreads();

    const int nquads = N_PAIRS / 4;
    const int stride = gridDim.x * blockDim.x;

    for (int t = blockIdx.x * blockDim.x + threadIdx.x; t < nquads; t += stride) {
        // ---- Streaming loads (evict-first: keep L1 for gathers) ----
        int4   vi = __ldcs(reinterpret_cast<const int4*>(idx_i) + t);
        int4   vj = __ldcs(reinterpret_cast<const int4*>(idx_j) + t);
        float4 vd = __ldcs(reinterpret_cast<const float4*>(d_ij) + t);
        int4   vs = __ldcs(reinterpret_cast<const int4*>(seg)   + t);

        // ---- Batch the 8 random gathers back-to-back (max MLP) ----
        float qi0 = __ldg(q + vi.x), qj0 = __ldg(q + vj.x);
        float qi1 = __ldg(q + vi.y), qj1 = __ldg(q + vj.y);
        float qi2 = __ldg(q + vi.z), qj2 = __ldg(q + vj.z);
        float qi3 = __ldg(q + vi.w), qj3 = __ldg(q + vj.w);

        // ---- Compute; fold unique mask as a multiply (no control flow) ----
        float m0 = (vi.x < vj.x) ? 1.0f : 0.0f;
        float m1 = (vi.y < vj.y) ? 1.0f : 0.0f;
        float m2 = (vi.z < vj.z) ? 1.0f : 0.0f;
        float m3 = (vi.w < vj.w) ? 1.0f : 0.0f;

        float c0 = qi0 * qj0 * chi_of_d(vd.x) * m0;
        float c1 = qi1 * qj1 * chi_of_d(vd.y) * m1;
        float c2 = qi2 * qj2 * chi_of_d(vd.z) * m2;
        float c3 = qi3 * qj3 * chi_of_d(vd.w) * m3;

        // ---- Unconditional SMEM scatter (no BSSY/BSYNC; +0.0f is exact) ----
        atomicAdd(&acc[vs.x], c0);
        atomicAdd(&acc[vs.y], c1);
        atomicAdd(&acc[vs.z], c2);
        atomicAdd(&acc[vs.w], c3);
    }

    __syncthreads();

    // Flush block-private histogram (out already holds pse*KE)
    for (int m = threadIdx.x; m < N_MOLS; m += blockDim.x) {
        float v = acc[m];
        if (v != 0.0f)
            atomicAdd(&out[m], v * KE_CONST);
    }
}

// ---------------------------------------------------------------------------
// Launch
// ---------------------------------------------------------------------------
extern "C" void kernel_launch(void* const* d_in, const int* in_sizes, int n_in,
                              void* d_out, int out_size) {
    const float* q    = (const float*)d_in[0];           // per_atom_charge [N_ATOMS]
    const int*   pidx = (const int*)  d_in[1];           // pair_indices [2, N_PAIRS]
    const float* dij  = (const float*)d_in[2];           // d_ij [N_PAIRS]
    const int*   seg  = (const int*)  d_in[3];           // atomic_subsystem_indices [N_PAIRS]
    const float* pse  = (const float*)d_in[4];           // per_system_energy [N_MOLS]
    float* out = (float*)d_out;

    const int* idx_i = pidx;
    const int* idx_j = pidx + N_PAIRS;

    init_out_kernel<<<(N_MOLS + 255) / 256, 256>>>(pse, out);

    // Proven config: 4 blocks/SM x 148 SMs, 512 threads, 64 warps/SM.
    const int blocks  = 592;
    const int threads = 512;
    coulomb_pairs_kernel<<<blocks, threads>>>(q, idx_i, idx_j, dij, seg, out);
}